// round 8
// baseline (speedup 1.0000x reference)
#include <cuda_runtime.h>
#include <cstdint>

// Problem constants
#define NIMG   32768
#define CC     14
#define CELLS  (32768 * 6 * 8)           // 1,572,864
#define TPB    256
#define CPT    512                       // cells per tile (2 per thread)
#define TILES  (CELLS / CPT)             // 3072, exact
#define V4PT   (CPT * CC / 4)            // 1792 float4 per tensor per tile
#define LPT    (V4PT / TPB)              // 7 float4 loads per thread per tensor

#define LAMBDA_COORD 8.0f
#define LAMBDA_NOOBJ 1.0f
#define LAMBDA_CLASS 0.7f
#define EPSV 1e-10f

__device__ float    g_partials[TILES];
__device__ unsigned g_count = 0;         // self-resetting block-arrival counter

__device__ __forceinline__ float iou_f(float x1, float y1, float sw1, float sh1,
                                       float x2, float y2, float sw2, float sh2) {
    float w1 = sw1 * sw1, h1 = sh1 * sh1;
    float w2 = sw2 * sw2, h2 = sh2 * sh2;
    float left  = fmaxf(x1 - 0.5f * w1, x2 - 0.5f * w2);
    float right = fminf(x1 + 0.5f * w1, x2 + 0.5f * w2);
    float top   = fmaxf(y1 - 0.5f * h1, y2 - 0.5f * h2);
    float bot   = fminf(y1 + 0.5f * h1, y2 + 0.5f * h2);
    float inter = fmaxf(right - left, 0.0f) * fmaxf(bot - top, 0.0f);
    float uni   = w1 * h1 + w2 * h2 - inter;
    return inter / (uni + EPSV);
}

// Loss for one cell given its 14 channels of o and g.
__device__ __forceinline__ float cell_loss14(const float* o, const float* g) {
    float o0 = o[0], o1 = o[1], oc2 = o[2], o3 = o[3], o4 = o[4];
    float o5 = o[5], o6 = o[6], o7 = o[7], o8 = o[8], o9 = o[9];
    float g0 = g[0], g1 = g[1], gc2 = g[2], g3 = g[3], g4 = g[4];
    float g5 = g[5], g6 = g[6], g7 = g[7], g8 = g[8], g9 = g[9];

    float obj   = (g4 > 0.0f) ? 1.0f : 0.0f;
    float noobj = 1.0f - obj;

    float iou0 = iou_f(o0, o1, oc2, o3, g0, g1, gc2, g3);
    float iou1 = iou_f(o5, o6, o7, o8, g0, g1, gc2, g3);

    bool  sel1    = (iou1 > iou0);     // argmax tie-break: first index wins
    float max_iou = sel1 ? iou1 : iou0;

    float pr0 = sel1 ? o5 : o0;
    float pr1 = sel1 ? o6 : o1;
    float pr2 = sel1 ? o7 : oc2;
    float pr3 = sel1 ? o8 : o3;
    float pr4 = sel1 ? o9 : o4;
    float po4 = sel1 ? o4 : o9;

    float gr0 = sel1 ? g5 : g0;
    float gr1 = sel1 ? g6 : g1;
    float gr2 = sel1 ? g7 : gc2;
    float gr3 = sel1 ? g8 : g3;
    float go4 = sel1 ? g4 : g9;

    float d4 = o4 - g4, d9 = o9 - g9;
    float no_loss = noobj * (d4 * d4 + d9 * d9);

    float ec = pr4 - max_iou;
    float conf_loss = ec * ec;

    float l0 = pr0 - gr0, l1 = pr1 - gr1, l2 = pr2 - gr2, l3 = pr3 - gr3;
    float loc_loss = l0 * l0 + l1 * l1 + l2 * l2 + l3 * l3;

    float eo = po4 - go4;
    float nbc_loss = eo * eo;

    float c0 = o[10] - g[10], c1 = o[11] - g[11];
    float c2v = o[12] - g[12], c3 = o[13] - g[13];
    float cls_loss = c0 * c0 + c1 * c1 + c2v * c2v + c3 * c3;

    return LAMBDA_NOOBJ * no_loss
         + obj * (conf_loss + LAMBDA_COORD * loc_loss
                  + LAMBDA_NOOBJ * nbc_loss + LAMBDA_CLASS * cls_loss);
}

__global__ void __launch_bounds__(TPB)
yolo_kernel(const float4* __restrict__ out4, const float4* __restrict__ gt4,
            float* __restrict__ d_out) {
    __shared__ float4 s_o[V4PT];
    __shared__ float4 s_g[V4PT];
    __shared__ float  warpsum[TPB / 32];
    __shared__ bool   is_last;

    const unsigned tid  = threadIdx.x;
    const unsigned lane = tid & 31u;
    const unsigned wid  = tid >> 5;
    const unsigned tile = blockIdx.x;
    const size_t   bv   = (size_t)tile * V4PT;

    // Stage: 7+7 independent streaming LDG.128, then 7+7 STS.128. Linear layout.
    float4 lo[LPT], lg[LPT];
#pragma unroll
    for (int i = 0; i < LPT; ++i) lo[i] = __ldcs(&out4[bv + i * TPB + tid]);
#pragma unroll
    for (int i = 0; i < LPT; ++i) lg[i] = __ldcs(&gt4[bv + i * TPB + tid]);
#pragma unroll
    for (int i = 0; i < LPT; ++i) s_o[i * TPB + tid] = lo[i];
#pragma unroll
    for (int i = 0; i < LPT; ++i) s_g[i * TPB + tid] = lg[i];
    __syncthreads();

    // Two cells per thread: cell pair base = tid*112 bytes = 7 aligned float4.
    // LDS.128 pattern lane*112+16i: conflict-free (banks 28L..28L+3 mod 32).
    float co[28], cg[28];
    {
        const float4* po = (const float4*)((const char*)s_o + tid * 112u);
        const float4* pg = (const float4*)((const char*)s_g + tid * 112u);
#pragma unroll
        for (int j = 0; j < 7; ++j) {
            float4 v = po[j];
            co[4*j] = v.x; co[4*j+1] = v.y; co[4*j+2] = v.z; co[4*j+3] = v.w;
        }
#pragma unroll
        for (int j = 0; j < 7; ++j) {
            float4 v = pg[j];
            cg[4*j] = v.x; cg[4*j+1] = v.y; cg[4*j+2] = v.z; cg[4*j+3] = v.w;
        }
    }

    float cell = cell_loss14(co, cg) + cell_loss14(co + CC, cg + CC);

    // Fixed-order block reduction
#pragma unroll
    for (int off = 16; off > 0; off >>= 1)
        cell += __shfl_down_sync(0xFFFFFFFFu, cell, off);
    if (lane == 0) warpsum[wid] = cell;
    __syncthreads();

    if (tid == 0) {
        float p = 0.0f;
#pragma unroll
        for (int w = 0; w < TPB / 32; ++w) p += warpsum[w];
        g_partials[tile] = p;
        __threadfence();
        unsigned old = atomicAdd(&g_count, 1u);
        is_last = (old == gridDim.x - 1);
    }
    __syncthreads();

    // Last-arriving block: deterministic final reduction of 3072 partials.
    if (is_last) {
        double dacc = 0.0;
#pragma unroll 4
        for (int i = tid; i < TILES; i += TPB)
            dacc += (double)__ldcg(&g_partials[i]);
#pragma unroll
        for (int off = 16; off > 0; off >>= 1)
            dacc += __shfl_down_sync(0xFFFFFFFFu, dacc, off);

        __shared__ double dws[TPB / 32];
        if (lane == 0) dws[wid] = dacc;
        __syncthreads();
        if (tid == 0) {
            double total = 0.0;
#pragma unroll
            for (int w = 0; w < TPB / 32; ++w) total += dws[w];
            d_out[0] = (float)(total / (double)NIMG);
            g_count = 0;                  // reset for next graph replay
        }
    }
}

extern "C" void kernel_launch(void* const* d_in, const int* in_sizes, int n_in,
                              void* d_out, int out_size) {
    const float4* output = (const float4*)d_in[0];
    const float4* gtruth = (const float4*)d_in[1];
    float* outp = (float*)d_out;

    yolo_kernel<<<TILES, TPB>>>(output, gtruth, outp);
}

// round 9
// speedup vs baseline: 1.0920x; 1.0920x over previous
#include <cuda_runtime.h>
#include <cstdint>

// Problem constants
#define NIMG   32768
#define CC     14
#define CELLS  (32768 * 6 * 8)           // 1,572,864
#define TPB    256
#define TILES  (CELLS / TPB)             // 6144, exact
#define PAD    15                        // stride-15 smem: coprime with 32

#define LAMBDA_COORD 8.0f
#define LAMBDA_NOOBJ 1.0f
#define LAMBDA_CLASS 0.7f
#define EPSV 1e-10f

__device__ float    g_partials[TILES];
__device__ unsigned g_count = 0;         // self-resetting block-arrival counter

__device__ __forceinline__ float iou_f(float x1, float y1, float sw1, float sh1,
                                       float x2, float y2, float sw2, float sh2) {
    float w1 = sw1 * sw1, h1 = sh1 * sh1;
    float w2 = sw2 * sw2, h2 = sh2 * sh2;
    float left  = fmaxf(x1 - 0.5f * w1, x2 - 0.5f * w2);
    float right = fminf(x1 + 0.5f * w1, x2 + 0.5f * w2);
    float top   = fmaxf(y1 - 0.5f * h1, y2 - 0.5f * h2);
    float bot   = fminf(y1 + 0.5f * h1, y2 + 0.5f * h2);
    float inter = fmaxf(right - left, 0.0f) * fmaxf(bot - top, 0.0f);
    float uni   = w1 * h1 + w2 * h2 - inter;
    return inter / (uni + EPSV);
}

__global__ void yolo_cell_kernel(const float* __restrict__ out,
                                 const float* __restrict__ gt,
                                 float* __restrict__ d_out) {
    __shared__ float s_o[TPB * PAD];
    __shared__ float s_g[TPB * PAD];
    __shared__ float warpsum[TPB / 32];
    __shared__ bool  is_last;

    const unsigned tid  = threadIdx.x;
    const unsigned lane = tid & 31u;
    const unsigned wid  = tid >> 5;
    const unsigned tile = blockIdx.x;
    const size_t base = (size_t)tile * (TPB * CC);

    // R1's measured-best memory engine: 14 coalesced scalar-load passes per
    // tensor, scattered into stride-15 padded smem (magic-mul for /14, %14).
#pragma unroll
    for (int i = 0; i < CC; ++i) {
        unsigned f = i * TPB + tid;          // 0..3583
        unsigned c = f / 14u;
        unsigned k = f - c * 14u;
        s_o[c * PAD + k] = out[base + f];
        s_g[c * PAD + k] = gt[base + f];
    }
    __syncthreads();

    const float* o = &s_o[tid * PAD];
    const float* g = &s_g[tid * PAD];

    float o0 = o[0], o1 = o[1], o2 = o[2], o3 = o[3], o4 = o[4];
    float o5 = o[5], o6 = o[6], o7 = o[7], o8 = o[8], o9 = o[9];
    float g0 = g[0], g1 = g[1], g2 = g[2], g3 = g[3], g4 = g[4];
    float g5 = g[5], g6 = g[6], g7 = g[7], g8 = g[8], g9 = g[9];

    float obj   = (g4 > 0.0f) ? 1.0f : 0.0f;
    float noobj = 1.0f - obj;

    float iou0 = iou_f(o0, o1, o2, o3, g0, g1, g2, g3);
    float iou1 = iou_f(o5, o6, o7, o8, g0, g1, g2, g3);

    bool  sel1    = (iou1 > iou0);     // argmax tie-break: first index wins
    float max_iou = sel1 ? iou1 : iou0;

    float pr0 = sel1 ? o5 : o0;
    float pr1 = sel1 ? o6 : o1;
    float pr2 = sel1 ? o7 : o2;
    float pr3 = sel1 ? o8 : o3;
    float pr4 = sel1 ? o9 : o4;
    float po4 = sel1 ? o4 : o9;

    float gr0 = sel1 ? g5 : g0;
    float gr1 = sel1 ? g6 : g1;
    float gr2 = sel1 ? g7 : g2;
    float gr3 = sel1 ? g8 : g3;
    float go4 = sel1 ? g4 : g9;

    float d4 = o4 - g4, d9 = o9 - g9;
    float no_loss = noobj * (d4 * d4 + d9 * d9);

    float ec = pr4 - max_iou;
    float conf_loss = ec * ec;

    float l0 = pr0 - gr0, l1 = pr1 - gr1, l2 = pr2 - gr2, l3 = pr3 - gr3;
    float loc_loss = l0 * l0 + l1 * l1 + l2 * l2 + l3 * l3;

    float eo = po4 - go4;
    float nbc_loss = eo * eo;

    float c0 = o[10] - g[10], c1 = o[11] - g[11], c2 = o[12] - g[12], c3 = o[13] - g[13];
    float cls_loss = c0 * c0 + c1 * c1 + c2 * c2 + c3 * c3;

    float cell = LAMBDA_NOOBJ * no_loss
               + obj * (conf_loss + LAMBDA_COORD * loc_loss
                        + LAMBDA_NOOBJ * nbc_loss + LAMBDA_CLASS * cls_loss);

    // Fixed-order block reduction (deterministic)
#pragma unroll
    for (int off = 16; off > 0; off >>= 1)
        cell += __shfl_down_sync(0xFFFFFFFFu, cell, off);
    if (lane == 0) warpsum[wid] = cell;
    __syncthreads();

    if (tid == 0) {
        float p = 0.0f;
#pragma unroll
        for (int w = 0; w < TPB / 32; ++w) p += warpsum[w];
        g_partials[tile] = p;
        __threadfence();
        unsigned old = atomicAdd(&g_count, 1u);
        is_last = (old == gridDim.x - 1);
    }
    __syncthreads();

    // Last-arriving block: deterministic final reduction of 6144 partials.
    if (is_last) {
        double dacc = 0.0;
#pragma unroll 8
        for (int i = tid; i < TILES; i += TPB)
            dacc += (double)__ldcg(&g_partials[i]);
#pragma unroll
        for (int off = 16; off > 0; off >>= 1)
            dacc += __shfl_down_sync(0xFFFFFFFFu, dacc, off);

        __shared__ double dws[TPB / 32];
        if (lane == 0) dws[wid] = dacc;
        __syncthreads();
        if (tid == 0) {
            double total = 0.0;
#pragma unroll
            for (int w = 0; w < TPB / 32; ++w) total += dws[w];
            d_out[0] = (float)(total / (double)NIMG);
            g_count = 0;                  // reset for next graph replay
        }
    }
}

extern "C" void kernel_launch(void* const* d_in, const int* in_sizes, int n_in,
                              void* d_out, int out_size) {
    const float* output = (const float*)d_in[0];
    const float* gtruth = (const float*)d_in[1];
    float* outp = (float*)d_out;

    yolo_cell_kernel<<<TILES, TPB>>>(output, gtruth, outp);
}

// round 10
// speedup vs baseline: 1.2202x; 1.1174x over previous
#include <cuda_runtime.h>
#include <cstdint>

// Problem constants
#define NIMG   32768
#define CC     14
#define CELLS  (32768 * 6 * 8)           // 1,572,864
#define TPB    256
#define CPT    256                       // cells per tile (1 per thread)
#define TILES  (CELLS / CPT)             // 6144, exact
#define V4PT   (CPT * CC / 4)            // 896 float4 per tensor per tile
#define GRIDN  592                       // 148 SMs x 4 resident blocks

#define LAMBDA_COORD 8.0f
#define LAMBDA_NOOBJ 1.0f
#define LAMBDA_CLASS 0.7f
#define EPSV 1e-10f

__device__ float    g_partials[GRIDN];
__device__ unsigned g_count = 0;         // self-resetting block-arrival counter

__device__ __forceinline__ void cp16(float4* sdst, const float4* gsrc) {
    uint32_t s = (uint32_t)__cvta_generic_to_shared(sdst);
    asm volatile("cp.async.cg.shared.global [%0], [%1], 16;\n" :: "r"(s), "l"(gsrc));
}

// Stage one tile (both tensors) into an smem buffer. 896 = 3*256 + 128.
__device__ __forceinline__ void stage_tile(float4* so, float4* sg,
                                           const float4* __restrict__ out4,
                                           const float4* __restrict__ gt4,
                                           size_t bv, unsigned tid) {
#pragma unroll
    for (int i = 0; i < 3; ++i) {
        unsigned v = i * TPB + tid;
        cp16(so + v, out4 + bv + v);
        cp16(sg + v, gt4 + bv + v);
    }
    if (tid < V4PT - 3 * TPB) {
        unsigned v = 3 * TPB + tid;
        cp16(so + v, out4 + bv + v);
        cp16(sg + v, gt4 + bv + v);
    }
    asm volatile("cp.async.commit_group;\n");
}

__device__ __forceinline__ float iou_f(float x1, float y1, float sw1, float sh1,
                                       float x2, float y2, float sw2, float sh2) {
    float w1 = sw1 * sw1, h1 = sh1 * sh1;
    float w2 = sw2 * sw2, h2 = sh2 * sh2;
    float left  = fmaxf(x1 - 0.5f * w1, x2 - 0.5f * w2);
    float right = fminf(x1 + 0.5f * w1, x2 + 0.5f * w2);
    float top   = fmaxf(y1 - 0.5f * h1, y2 - 0.5f * h2);
    float bot   = fminf(y1 + 0.5f * h1, y2 + 0.5f * h2);
    float inter = fmaxf(right - left, 0.0f) * fmaxf(bot - top, 0.0f);
    float uni   = w1 * h1 + w2 * h2 - inter;
    return inter / (uni + EPSV);
}

__device__ __forceinline__ float cell_loss(const float4* sbuf, unsigned tid) {
    // Cell base = tid*56 bytes within each tensor half; o first, g at +V4PT float4.
    const float2* o2 = (const float2*)((const char*)sbuf + tid * 56u);
    const float2* g2 = (const float2*)((const char*)(sbuf + V4PT) + tid * 56u);

    float2 a0 = o2[0], a1 = o2[1], a2 = o2[2], a3 = o2[3], a4 = o2[4];
    float2 b0 = g2[0], b1 = g2[1], b2 = g2[2], b3 = g2[3], b4 = g2[4];

    float o0 = a0.x, o1 = a0.y, oc2 = a1.x, o3 = a1.y, o4 = a2.x;
    float o5 = a2.y, o6 = a3.x, o7 = a3.y, o8 = a4.x, o9 = a4.y;
    float g0 = b0.x, g1 = b0.y, gc2 = b1.x, g3 = b1.y, g4 = b2.x;
    float g5 = b2.y, g6 = b3.x, g7 = b3.y, g8 = b4.x, g9 = b4.y;

    float obj   = (g4 > 0.0f) ? 1.0f : 0.0f;
    float noobj = 1.0f - obj;

    float iou0 = iou_f(o0, o1, oc2, o3, g0, g1, gc2, g3);
    float iou1 = iou_f(o5, o6, o7, o8, g0, g1, gc2, g3);

    bool  sel1    = (iou1 > iou0);     // argmax tie-break: first index wins
    float max_iou = sel1 ? iou1 : iou0;

    float pr0 = sel1 ? o5 : o0;
    float pr1 = sel1 ? o6 : o1;
    float pr2 = sel1 ? o7 : oc2;
    float pr3 = sel1 ? o8 : o3;
    float pr4 = sel1 ? o9 : o4;
    float po4 = sel1 ? o4 : o9;

    float gr0 = sel1 ? g5 : g0;
    float gr1 = sel1 ? g6 : g1;
    float gr2 = sel1 ? g7 : gc2;
    float gr3 = sel1 ? g8 : g3;
    float go4 = sel1 ? g4 : g9;

    float d4 = o4 - g4, d9 = o9 - g9;
    float no_loss = noobj * (d4 * d4 + d9 * d9);

    float ec = pr4 - max_iou;
    float conf_loss = ec * ec;

    float l0 = pr0 - gr0, l1 = pr1 - gr1, l2 = pr2 - gr2, l3 = pr3 - gr3;
    float loc_loss = l0 * l0 + l1 * l1 + l2 * l2 + l3 * l3;

    float eo = po4 - go4;
    float nbc_loss = eo * eo;

    float2 a5 = o2[5], a6 = o2[6];
    float2 b5 = g2[5], b6 = g2[6];
    float c0 = a5.x - b5.x, c1 = a5.y - b5.y, c2v = a6.x - b6.x, c3 = a6.y - b6.y;
    float cls_loss = c0 * c0 + c1 * c1 + c2v * c2v + c3 * c3;

    return LAMBDA_NOOBJ * no_loss
         + obj * (conf_loss + LAMBDA_COORD * loc_loss
                  + LAMBDA_NOOBJ * nbc_loss + LAMBDA_CLASS * cls_loss);
}

__global__ void __launch_bounds__(TPB, 4)
yolo_persistent_kernel(const float4* __restrict__ out4, const float4* __restrict__ gt4,
                       float* __restrict__ d_out) {
    // STATIC shared memory: exactly 56KB of buffers -> 4 blocks/SM.
    __shared__ float4 smem[2 * 2 * V4PT];    // [2 buffers][o:896 | g:896]
    __shared__ float  warpsum[TPB / 32];
    __shared__ bool   is_last;

    const unsigned tid  = threadIdx.x;
    const unsigned lane = tid & 31u;
    const unsigned wid  = tid >> 5;
    const unsigned bid  = blockIdx.x;

    float4* buf0 = smem;
    float4* buf1 = smem + 2 * V4PT;

    float acc = 0.0f;

    int cur = (int)bid;
    if (cur < TILES)
        stage_tile(buf0, buf0 + V4PT, out4, gt4, (size_t)cur * V4PT, tid);

    unsigned b = 0;
    while (cur < TILES) {
        int nxt = cur + GRIDN;
        bool have_nxt = (nxt < TILES);
        float4* nbuf = b ? buf0 : buf1;
        float4* cbuf = b ? buf1 : buf0;
        if (have_nxt)
            stage_tile(nbuf, nbuf + V4PT, out4, gt4, (size_t)nxt * V4PT, tid);

        // Wait for current tile's copy (pending groups: next's if staged).
        if (have_nxt) asm volatile("cp.async.wait_group 1;\n");
        else          asm volatile("cp.async.wait_group 0;\n");
        __syncthreads();

        acc += cell_loss(cbuf, tid);

        __syncthreads();                 // all reads done before cbuf is re-staged
        cur = nxt;
        b ^= 1u;
    }

    // Fixed-order block reduction
#pragma unroll
    for (int off = 16; off > 0; off >>= 1)
        acc += __shfl_down_sync(0xFFFFFFFFu, acc, off);
    if (lane == 0) warpsum[wid] = acc;
    __syncthreads();

    if (tid == 0) {
        float p = 0.0f;
#pragma unroll
        for (int w = 0; w < TPB / 32; ++w) p += warpsum[w];
        g_partials[bid] = p;
        __threadfence();
        unsigned old = atomicAdd(&g_count, 1u);
        is_last = (old == gridDim.x - 1);
    }
    __syncthreads();

    if (is_last) {
        double dacc = 0.0;
        for (int i = tid; i < GRIDN; i += TPB)
            dacc += (double)__ldcg(&g_partials[i]);
#pragma unroll
        for (int off = 16; off > 0; off >>= 1)
            dacc += __shfl_down_sync(0xFFFFFFFFu, dacc, off);

        __shared__ double dws[TPB / 32];
        if (lane == 0) dws[wid] = dacc;
        __syncthreads();
        if (tid == 0) {
            double total = 0.0;
#pragma unroll
            for (int w = 0; w < TPB / 32; ++w) total += dws[w];
            d_out[0] = (float)(total / (double)NIMG);
            g_count = 0;                  // reset for next graph replay
        }
    }
}

extern "C" void kernel_launch(void* const* d_in, const int* in_sizes, int n_in,
                              void* d_out, int out_size) {
    const float4* output = (const float4*)d_in[0];
    const float4* gtruth = (const float4*)d_in[1];
    float* outp = (float*)d_out;

    yolo_persistent_kernel<<<GRIDN, TPB>>>(output, gtruth, outp);
}